// round 7
// baseline (speedup 1.0000x reference)
#include <cuda_runtime.h>
#include <cstdint>

#define Bb 16
#define Nn 64
#define Hh 256
#define Tt 5
#define ROWS (Bb*Nn*Nn)      // 16384
#define BNH  (Bb*Nn*Hh)      // 262144

typedef unsigned long long ull;

// ---- device scratch ----
__device__ float g_prop [BNH];
__device__ float g_msg  [Tt*BNH];
__device__ float g_Wc   [Hh*Hh];
__device__ float g_A    [ROWS*512];   // gathered A rows [maxpool | fimg1]
__device__ float g_fi2v [Bb*Hh];
__device__ float g_fsslv[Bb*Hh];
__device__ float g_biasb[Bb*Hh];
__device__ int   g_rows [ROWS];
__device__ int   g_count;

// ---- packed f32x2 helpers ----
__device__ __forceinline__ ull pack2(float lo, float hi) {
    ull r; asm("mov.b64 %0, {%1,%2};" : "=l"(r) : "f"(lo), "f"(hi)); return r;
}
__device__ __forceinline__ void fma2(ull& d, ull a, ull b) {
    asm("fma.rn.f32x2 %0, %1, %2, %0;" : "+l"(d) : "l"(a), "l"(b));
}
__device__ __forceinline__ void unpack2(ull v, float& lo, float& hi) {
    asm("mov.b64 {%0,%1}, %2;" : "=f"(lo), "=f"(hi) : "l"(v));
}

// ---- cp.async helpers ----
__device__ __forceinline__ uint32_t sptr(const void* p) {
    return (uint32_t)__cvta_generic_to_shared(p);
}
__device__ __forceinline__ void cpa16(uint32_t dst, const void* src, int szbytes) {
    asm volatile("cp.async.ca.shared.global [%0], [%1], 16, %2;"
                 :: "r"(dst), "l"(src), "r"(szbytes));
}
#define CP_COMMIT() asm volatile("cp.async.commit_group;")
template<int N> __device__ __forceinline__ void cp_wait() {
    asm volatile("cp.async.wait_group %0;" :: "n"(N));
}

// ============================================================
// GEMM: C[M,256] = A[M,K] @ W[K,256] (+bias)   [R2 verbatim — known good]
// ============================================================
__global__ __launch_bounds__(256) void gemm_kernel(
    const float* __restrict__ A, const float* __restrict__ W,
    const float* __restrict__ bias, float* __restrict__ C,
    int M, int K)
{
    __shared__ __align__(16) float AS[2][32][36];
    __shared__ __align__(16) float BS[2][32][64];
    int m0 = blockIdx.x * 32, n0 = blockIdx.y * 64;
    int tid = threadIdx.x;

    int ar = tid >> 3, ac = tid & 7;
    int bk0 = tid >> 4, bc0 = tid & 15;

    auto issue = [&](int s, int k0) {
        bool aok = (m0 + ar) < M;
        const float* asrc = A + (size_t)(aok ? (m0 + ar) : 0) * K + k0 + ac*4;
        cpa16(sptr(&AS[s][ar][ac*4]), asrc, aok ? 16 : 0);
        #pragma unroll
        for (int q = 0; q < 2; q++) {
            int kk = bk0 + q*16;
            cpa16(sptr(&BS[s][kk][bc0*4]), W + (size_t)(k0+kk)*256 + n0 + bc0*4, 16);
        }
        CP_COMMIT();
    };

    int tx = tid & 15, ty = tid >> 4;
    ull acc[2][2] = {};

    issue(0, 0);
    int nt = K >> 5;
    for (int t = 0; t < nt; t++) {
        if (t + 1 < nt) { issue((t+1)&1, (t+1)*32); cp_wait<1>(); }
        else            { cp_wait<0>(); }
        __syncthreads();
        int s = t & 1;
        #pragma unroll
        for (int k = 0; k < 32; k++) {
            float a0 = AS[s][ty*2+0][k];
            float a1 = AS[s][ty*2+1][k];
            float4 b = *(float4*)&BS[s][k][tx*4];
            ull bp0 = pack2(b.x, b.y), bp1 = pack2(b.z, b.w);
            ull aa0 = pack2(a0, a0),   aa1 = pack2(a1, a1);
            fma2(acc[0][0], aa0, bp0); fma2(acc[0][1], aa0, bp1);
            fma2(acc[1][0], aa1, bp0); fma2(acc[1][1], aa1, bp1);
        }
        __syncthreads();
    }

    #pragma unroll
    for (int q = 0; q < 2; q++) {
        int gr = m0 + ty*2 + q;
        if (gr < M) {
            float v[4];
            unpack2(acc[q][0], v[0], v[1]);
            unpack2(acc[q][1], v[2], v[3]);
            #pragma unroll
            for (int c = 0; c < 4; c++) {
                int gc = n0 + tx*4 + c;
                float o = v[c];
                if (bias) o += bias[gc];
                C[(size_t)gr*256 + gc] = o;
            }
        }
    }
}

// ============================================================
// Scan aggregation  [R2 verbatim — known good]
// ============================================================
__global__ __launch_bounds__(256) void agg_kernel(int t, const int* __restrict__ mask)
{
    int bi = blockIdx.x;
    int b  = bi >> 6;
    int h  = threadIdx.x;
    __shared__ int msk[64];
    if (h < 64) msk[h] = mask[bi*64 + h];
    __syncthreads();

    const float* msgb = g_msg + (size_t)(t*Bb + b) * Nn * Hh;
    float mi = msgb[(bi & 63)*Hh + h];
    float acc = 0.f;
    #pragma unroll 8
    for (int j = 0; j < 64; j++) {
        if (msk[j]) {
            float mj = __ldg(&msgb[j*Hh + h]);
            acc += fmaxf(mi + mj, 0.f) * mj;
        }
    }
    g_prop[(size_t)bi*Hh + h] += fmaxf(mi + acc, 0.f);
}

// ============================================================
// Per-batch effective bias  [R2 verbatim — known good]
// ============================================================
__global__ __launch_bounds__(256) void biask_kernel(
    const float* __restrict__ b1, const float* __restrict__ bimg,
    const float* __restrict__ w1)
{
    int b = blockIdx.x;
    int n = blockIdx.y*64 + (threadIdx.x & 63);
    int part = threadIdx.x >> 6;
    __shared__ float red[4][64];
    const float* f2 = g_fi2v  + b*256;
    const float* f3 = g_fsslv + b*256;
    float s = 0.f;
    for (int h = part; h < 256; h += 4) {
        s += bimg[h] * __ldg(&w1[(256+h)*256 + n]);
        s += f2[h]   * __ldg(&w1[(512+h)*256 + n]);
        s += f3[h]   * __ldg(&w1[(768+h)*256 + n]);
    }
    red[part][threadIdx.x & 63] = s;
    __syncthreads();
    if (part == 0) {
        int l = threadIdx.x & 63;
        g_biasb[b*256 + n] = b1[n] + red[0][l] + red[1][l] + red[2][l] + red[3][l];
    }
}

// ============================================================
// Reset + compaction + output zero-fill  [R2 verbatim — known good]
// ============================================================
__global__ void reset_kernel() { g_count = 0; }

__global__ __launch_bounds__(256) void compact_kernel(
    const int* __restrict__ mask, float* __restrict__ out)
{
    int r = blockIdx.x * 256 + threadIdx.x;
    float4 z = make_float4(0.f, 0.f, 0.f, 0.f);
    float4* o = (float4*)(out + (size_t)r * 8);
    o[0] = z; o[1] = z;
    if (mask[r] != 0) {
        int p = atomicAdd(&g_count, 1);
        g_rows[p] = r;
    }
}

// ============================================================
// Gather A rows = [maxpool | fimg1] (dead simple, coalesced).
// One block per compacted row slot (rounded up to 32); 1 thread/element.
// ============================================================
__global__ __launch_bounds__(256) void gather_kernel(
    const float* __restrict__ fimg1)
{
    int cnt = g_count;
    int idx = blockIdx.x;
    if (idx >= ((cnt + 31) & ~31)) return;
    int cl  = min(idx, cnt - 1);
    int row = g_rows[cl];
    int b = row >> 12, i = (row >> 6) & 63, j = row & 63;
    const float* mi = g_msg + (size_t)(b*64 + i) * 256;
    const float* mj = g_msg + (size_t)(b*64 + j) * 256;
    int h = threadIdx.x;
    float m = -1e30f;
    #pragma unroll
    for (int t = 0; t < Tt; t++)
        m = fmaxf(m, __ldg(&mi[(size_t)t*BNH + h]) + __ldg(&mj[(size_t)t*BNH + h]));
    g_A[(size_t)idx*512 + h]       = fmaxf(m, 0.f);
    g_A[(size_t)idx*512 + 256 + h] = __ldg(&fimg1[(size_t)row*256 + h]);
}

// ============================================================
// Fuse  [R2 verbatim EXCEPT A tile reads g_A instead of in-loop gen]
// BM=32, BN=256, BK=32, 256 threads, 2 CTAs/SM.
// ============================================================
__global__ __launch_bounds__(256, 2) void fuse_kernel(
    const float* __restrict__ w1, const float* __restrict__ w2,
    const float* __restrict__ b2, float* __restrict__ out)
{
    __shared__ ull As2[32][34];                  // [k][row], packed-dup
    __shared__ __align__(16) float Bs[32][264];  // [k][n]
    __shared__ int sRow[32], sB[32];

    int cnt = g_count;
    int m0  = blockIdx.x * 32;
    if (m0 >= cnt) return;
    int tid = threadIdx.x;

    if (tid < 32) {
        int idx = m0 + tid;
        int cl  = (idx < cnt) ? idx : (cnt - 1);
        int row = g_rows[cl];
        sRow[tid] = row;
        sB[tid]   = row >> 12;
    }
    __syncthreads();

    int tx = tid & 31, ty = tid >> 5;   // 8 cols (tx*8), 4 rows (ty*4)
    ull acc[4][4];
    #pragma unroll
    for (int q = 0; q < 4; q++)
        #pragma unroll
        for (int c = 0; c < 4; c++) acc[q][c] = 0ULL;

    for (int k0 = 0; k0 < 512; k0 += 32) {
        const float* Bsrc = (k0 < 256) ? (w1 + (size_t)k0*256)
                                       : (g_Wc + (size_t)(k0-256)*256);
        #pragma unroll
        for (int p = 0; p < 8; p++) {
            int c = p*256 + tid; int kk = c >> 6, c4 = c & 63;
            *(float4*)&Bs[kk][c4*4] = *(const float4*)&Bsrc[(size_t)kk*256 + c4*4];
        }
        // A tile: plain coalesced read of gathered rows
        #pragma unroll
        for (int p = 0; p < 4; p++) {
            int lin = p*256 + tid; int r = lin >> 5, kk = lin & 31;
            float v = __ldg(&g_A[(size_t)(m0 + r)*512 + k0 + kk]);
            As2[kk][r] = pack2(v, v);
        }
        __syncthreads();
        #pragma unroll
        for (int k = 0; k < 32; k++) {
            float4 b0 = *(float4*)&Bs[k][tx*8];
            float4 b1 = *(float4*)&Bs[k][tx*8 + 4];
            ull bp0 = pack2(b0.x,b0.y), bp1 = pack2(b0.z,b0.w);
            ull bp2 = pack2(b1.x,b1.y), bp3 = pack2(b1.z,b1.w);
            #pragma unroll
            for (int q = 0; q < 4; q++) {
                ull aa = As2[k][ty*4 + q];
                fma2(acc[q][0], aa, bp0); fma2(acc[q][1], aa, bp1);
                fma2(acc[q][2], aa, bp2); fma2(acc[q][3], aa, bp3);
            }
        }
        __syncthreads();
    }

    // per-lane w2 rows (cols tx*8..tx*8+7)  [R2 verbatim]
    float w2r[8][8];
    #pragma unroll
    for (int c = 0; c < 8; c++) {
        float4 u0 = __ldg((const float4*)&w2[(tx*8+c)*8]);
        float4 u1 = __ldg((const float4*)&w2[(tx*8+c)*8 + 4]);
        w2r[c][0]=u0.x; w2r[c][1]=u0.y; w2r[c][2]=u0.z; w2r[c][3]=u0.w;
        w2r[c][4]=u1.x; w2r[c][5]=u1.y; w2r[c][6]=u1.z; w2r[c][7]=u1.w;
    }

    #pragma unroll
    for (int q = 0; q < 4; q++) {
        int r = ty*4 + q;
        const float* bb = g_biasb + sB[r]*256 + tx*8;
        float h[8];
        unpack2(acc[q][0], h[0], h[1]);
        unpack2(acc[q][1], h[2], h[3]);
        unpack2(acc[q][2], h[4], h[5]);
        unpack2(acc[q][3], h[6], h[7]);
        float pe[8] = {0,0,0,0,0,0,0,0};
        #pragma unroll
        for (int c = 0; c < 8; c++) {
            float hv = fmaxf(h[c] + __ldg(&bb[c]), 0.f);
            #pragma unroll
            for (int e = 0; e < 8; e++) pe[e] += hv * w2r[c][e];
        }
        #pragma unroll
        for (int off = 16; off > 0; off >>= 1)
            #pragma unroll
            for (int e = 0; e < 8; e++)
                pe[e] += __shfl_xor_sync(0xffffffffu, pe[e], off);
        if (tx == 0 && (m0 + r) < cnt) {
            int row = sRow[r];
            #pragma unroll
            for (int e = 0; e < 8; e++)
                out[(size_t)row*8 + e] = pe[e] + __ldg(&b2[e]);
        }
    }
}

// ============================================================
extern "C" void kernel_launch(void* const* d_in, const int* in_sizes, int n_in,
                              void* d_out, int out_size)
{
    const float* feat_body    = (const float*)d_in[0];
    const float* feat_img_1   = (const float*)d_in[1];
    const float* feat_img_2   = (const float*)d_in[2];
    const float* feat_img_ssl = (const float*)d_in[3];
    const int*   full_mask    = (const int*)  d_in[4];
    const float* img_fc_w     = (const float*)d_in[5];
    const float* img_fc_b     = (const float*)d_in[6];
    const float* node_fc_w    = (const float*)d_in[7];
    const float* node_fc_b    = (const float*)d_in[8];
    const float* edge_fc_w1   = (const float*)d_in[9];
    const float* edge_fc_b1   = (const float*)d_in[10];
    const float* edge_fc_w2   = (const float*)d_in[11];
    const float* edge_fc_b2   = (const float*)d_in[12];
    float* out = (float*)d_out;

    void *pv;
    float *p_prop, *p_msg, *p_Wc, *p_fi2v, *p_fsslv;
    cudaGetSymbolAddress(&pv, g_prop);  p_prop  = (float*)pv;
    cudaGetSymbolAddress(&pv, g_msg);   p_msg   = (float*)pv;
    cudaGetSymbolAddress(&pv, g_Wc);    p_Wc    = (float*)pv;
    cudaGetSymbolAddress(&pv, g_fi2v);  p_fi2v  = (float*)pv;
    cudaGetSymbolAddress(&pv, g_fsslv); p_fsslv = (float*)pv;

    reset_kernel<<<1, 1>>>();
    compact_kernel<<<ROWS/256, 256>>>(full_mask, out);

    // prop0 = feat_body @ img_fc_w + img_fc_b
    gemm_kernel<<<dim3(32, 4), 256>>>(feat_body, img_fc_w, img_fc_b, p_prop,
                                      Bb*Nn, Hh);
    // scan
    for (int t = 0; t < Tt; t++) {
        gemm_kernel<<<dim3(32, 4), 256>>>(p_prop, node_fc_w + (size_t)t*Hh*Hh,
                                          node_fc_b + t*Hh,
                                          p_msg + (size_t)t*BNH, Bb*Nn, Hh);
        if (t < Tt - 1) agg_kernel<<<Bb*Nn, 256>>>(t, full_mask);
    }

    // folded weights / per-batch bias
    gemm_kernel<<<dim3(8, 4), 256>>>(img_fc_w, edge_fc_w1 + (size_t)Hh*Hh,
                                     nullptr, p_Wc, Hh, Hh);
    gemm_kernel<<<dim3(1, 4), 256>>>(feat_img_2, img_fc_w, img_fc_b, p_fi2v,
                                     Bb, Hh);
    gemm_kernel<<<dim3(1, 4), 256>>>(feat_img_ssl, img_fc_w, img_fc_b, p_fsslv,
                                     Bb, Hh);
    biask_kernel<<<dim3(Bb, 4), 256>>>(edge_fc_b1, img_fc_b, edge_fc_w1);

    // gather A rows, then R2 fuse with A read from g_A
    gather_kernel<<<ROWS, 256>>>(feat_img_1);
    fuse_kernel<<<ROWS/32, 256>>>(edge_fc_w1, edge_fc_w2, edge_fc_b2, out);
}

// round 9
// speedup vs baseline: 1.2103x; 1.2103x over previous
#include <cuda_runtime.h>
#include <cstdint>

#define Bb 16
#define Nn 64
#define Hh 256
#define Tt 5
#define ROWS (Bb*Nn*Nn)      // 16384
#define BNH  (Bb*Nn*Hh)      // 262144

typedef unsigned long long ull;

// ---- device scratch ----
__device__ float g_prop [BNH];
__device__ float g_msg  [Tt*BNH];
__device__ float g_Wc   [Hh*Hh];
__device__ float g_A    [ROWS*512];   // gathered A rows [maxpool | fimg1]
__device__ float g_fi2v [Bb*Hh];
__device__ float g_fsslv[Bb*Hh];
__device__ float g_biasb[Bb*Hh];
__device__ int   g_rows [ROWS];
__device__ int   g_count;

// ---- packed f32x2 helpers ----
__device__ __forceinline__ ull pack2(float lo, float hi) {
    ull r; asm("mov.b64 %0, {%1,%2};" : "=l"(r) : "f"(lo), "f"(hi)); return r;
}
__device__ __forceinline__ void fma2(ull& d, ull a, ull b) {
    asm("fma.rn.f32x2 %0, %1, %2, %0;" : "+l"(d) : "l"(a), "l"(b));
}
__device__ __forceinline__ void unpack2(ull v, float& lo, float& hi) {
    asm("mov.b64 {%0,%1}, %2;" : "=f"(lo), "=f"(hi) : "l"(v));
}

// ---- cp.async helpers ----
__device__ __forceinline__ uint32_t sptr(const void* p) {
    return (uint32_t)__cvta_generic_to_shared(p);
}
__device__ __forceinline__ void cpa16(uint32_t dst, const void* src, int szbytes) {
    asm volatile("cp.async.ca.shared.global [%0], [%1], 16, %2;"
                 :: "r"(dst), "l"(src), "r"(szbytes));
}
#define CP_COMMIT() asm volatile("cp.async.commit_group;")
template<int N> __device__ __forceinline__ void cp_wait() {
    asm volatile("cp.async.wait_group %0;" :: "n"(N));
}

// ============================================================
// GEMM: C[M,256] = A[M,K] @ W[K,256] (+bias)   [R2 verbatim — known good]
// ============================================================
__global__ __launch_bounds__(256) void gemm_kernel(
    const float* __restrict__ A, const float* __restrict__ W,
    const float* __restrict__ bias, float* __restrict__ C,
    int M, int K)
{
    __shared__ __align__(16) float AS[2][32][36];
    __shared__ __align__(16) float BS[2][32][64];
    int m0 = blockIdx.x * 32, n0 = blockIdx.y * 64;
    int tid = threadIdx.x;

    int ar = tid >> 3, ac = tid & 7;
    int bk0 = tid >> 4, bc0 = tid & 15;

    auto issue = [&](int s, int k0) {
        bool aok = (m0 + ar) < M;
        const float* asrc = A + (size_t)(aok ? (m0 + ar) : 0) * K + k0 + ac*4;
        cpa16(sptr(&AS[s][ar][ac*4]), asrc, aok ? 16 : 0);
        #pragma unroll
        for (int q = 0; q < 2; q++) {
            int kk = bk0 + q*16;
            cpa16(sptr(&BS[s][kk][bc0*4]), W + (size_t)(k0+kk)*256 + n0 + bc0*4, 16);
        }
        CP_COMMIT();
    };

    int tx = tid & 15, ty = tid >> 4;
    ull acc[2][2] = {};

    issue(0, 0);
    int nt = K >> 5;
    for (int t = 0; t < nt; t++) {
        if (t + 1 < nt) { issue((t+1)&1, (t+1)*32); cp_wait<1>(); }
        else            { cp_wait<0>(); }
        __syncthreads();
        int s = t & 1;
        #pragma unroll
        for (int k = 0; k < 32; k++) {
            float a0 = AS[s][ty*2+0][k];
            float a1 = AS[s][ty*2+1][k];
            float4 b = *(float4*)&BS[s][k][tx*4];
            ull bp0 = pack2(b.x, b.y), bp1 = pack2(b.z, b.w);
            ull aa0 = pack2(a0, a0),   aa1 = pack2(a1, a1);
            fma2(acc[0][0], aa0, bp0); fma2(acc[0][1], aa0, bp1);
            fma2(acc[1][0], aa1, bp0); fma2(acc[1][1], aa1, bp1);
        }
        __syncthreads();
    }

    #pragma unroll
    for (int q = 0; q < 2; q++) {
        int gr = m0 + ty*2 + q;
        if (gr < M) {
            float v[4];
            unpack2(acc[q][0], v[0], v[1]);
            unpack2(acc[q][1], v[2], v[3]);
            #pragma unroll
            for (int c = 0; c < 4; c++) {
                int gc = n0 + tx*4 + c;
                float o = v[c];
                if (bias) o += bias[gc];
                C[(size_t)gr*256 + gc] = o;
            }
        }
    }
}

// ============================================================
// Scan aggregation  [R2 verbatim — known good]
// ============================================================
__global__ __launch_bounds__(256) void agg_kernel(int t, const int* __restrict__ mask)
{
    int bi = blockIdx.x;
    int b  = bi >> 6;
    int h  = threadIdx.x;
    __shared__ int msk[64];
    if (h < 64) msk[h] = mask[bi*64 + h];
    __syncthreads();

    const float* msgb = g_msg + (size_t)(t*Bb + b) * Nn * Hh;
    float mi = msgb[(bi & 63)*Hh + h];
    float acc = 0.f;
    #pragma unroll 8
    for (int j = 0; j < 64; j++) {
        if (msk[j]) {
            float mj = __ldg(&msgb[j*Hh + h]);
            acc += fmaxf(mi + mj, 0.f) * mj;
        }
    }
    g_prop[(size_t)bi*Hh + h] += fmaxf(mi + acc, 0.f);
}

// ============================================================
// Per-batch effective bias  [R2 verbatim — known good]
// ============================================================
__global__ __launch_bounds__(256) void biask_kernel(
    const float* __restrict__ b1, const float* __restrict__ bimg,
    const float* __restrict__ w1)
{
    int b = blockIdx.x;
    int n = blockIdx.y*64 + (threadIdx.x & 63);
    int part = threadIdx.x >> 6;
    __shared__ float red[4][64];
    const float* f2 = g_fi2v  + b*256;
    const float* f3 = g_fsslv + b*256;
    float s = 0.f;
    for (int h = part; h < 256; h += 4) {
        s += bimg[h] * __ldg(&w1[(256+h)*256 + n]);
        s += f2[h]   * __ldg(&w1[(512+h)*256 + n]);
        s += f3[h]   * __ldg(&w1[(768+h)*256 + n]);
    }
    red[part][threadIdx.x & 63] = s;
    __syncthreads();
    if (part == 0) {
        int l = threadIdx.x & 63;
        g_biasb[b*256 + n] = b1[n] + red[0][l] + red[1][l] + red[2][l] + red[3][l];
    }
}

// ============================================================
// Reset + compaction + output zero-fill  [R2 verbatim — known good]
// ============================================================
__global__ void reset_kernel() { g_count = 0; }

__global__ __launch_bounds__(256) void compact_kernel(
    const int* __restrict__ mask, float* __restrict__ out)
{
    int r = blockIdx.x * 256 + threadIdx.x;
    float4 z = make_float4(0.f, 0.f, 0.f, 0.f);
    float4* o = (float4*)(out + (size_t)r * 8);
    o[0] = z; o[1] = z;
    if (mask[r] != 0) {
        int p = atomicAdd(&g_count, 1);
        g_rows[p] = r;
    }
}

// ============================================================
// Gather A rows = [maxpool | fimg1]  [R7 verbatim, 64-row rounding]
// ============================================================
__global__ __launch_bounds__(256) void gather_kernel(
    const float* __restrict__ fimg1)
{
    int cnt = g_count;
    int idx = blockIdx.x;
    if (idx >= ((cnt + 63) & ~63)) return;
    int cl  = min(idx, cnt - 1);
    int row = g_rows[cl];
    int b = row >> 12, i = (row >> 6) & 63, j = row & 63;
    const float* mi = g_msg + (size_t)(b*64 + i) * 256;
    const float* mj = g_msg + (size_t)(b*64 + j) * 256;
    int h = threadIdx.x;
    float m = -1e30f;
    #pragma unroll
    for (int t = 0; t < Tt; t++)
        m = fmaxf(m, __ldg(&mi[(size_t)t*BNH + h]) + __ldg(&mj[(size_t)t*BNH + h]));
    g_A[(size_t)idx*512 + h]       = fmaxf(m, 0.f);
    g_A[(size_t)idx*512 + 256 + h] = __ldg(&fimg1[(size_t)row*256 + h]);
}

// ============================================================
// fuse_v3b: C = relu(g_A @ [w1(0:256); g_Wc] + biasb) @ w2 + b2
// BM=64, BN=256, BK=32, 256 threads.
// smem = Bs 33.8KB + As 9.2KB (aliased as w2s in epilogue) + idx 0.5KB
//      = 43.5KB < 48KB.  No occupancy cap; smem epilogue (no shuffles).
// ============================================================
__global__ __launch_bounds__(256) void fuse_kernel(
    const float* __restrict__ w1, const float* __restrict__ w2,
    const float* __restrict__ b2, float* __restrict__ out)
{
    __shared__ __align__(16) float Bs[32][264];  // [k][n]; reused as Hs[32][264]
    __shared__ __align__(16) float As[32][72];   // [k][row]; reused as w2s[256*9]
    __shared__ int sRow[64], sB[64];

    int cnt = g_count;
    int m0  = blockIdx.x * 64;
    if (m0 >= cnt) return;
    int tid = threadIdx.x;

    if (tid < 64) {
        int cl  = min(m0 + tid, cnt - 1);
        int row = g_rows[cl];
        sRow[tid] = row;
        sB[tid]   = row >> 12;
    }
    __syncthreads();

    int tx = tid & 31, ty = tid >> 5;   // rows ty*8..+7; cols {tx*4+c, 128+tx*4+c}
    ull acc[8][4];
    #pragma unroll
    for (int q = 0; q < 8; q++)
        #pragma unroll
        for (int c = 0; c < 4; c++) acc[q][c] = 0ULL;

    for (int k0 = 0; k0 < 512; k0 += 32) {
        const float* Bsrc = (k0 < 256) ? (w1 + (size_t)k0*256)
                                       : (g_Wc + (size_t)(k0-256)*256);
        #pragma unroll
        for (int p = 0; p < 8; p++) {
            int c = p*256 + tid; int kk = c >> 6, c4 = c & 63;
            *(float4*)&Bs[kk][c4*4] = *(const float4*)&Bsrc[(size_t)kk*256 + c4*4];
        }
        #pragma unroll
        for (int p = 0; p < 8; p++) {
            int lin = p*256 + tid; int r = lin >> 5, kk = lin & 31;
            As[kk][r] = __ldg(&g_A[(size_t)(m0 + r)*512 + k0 + kk]);
        }
        __syncthreads();
        #pragma unroll
        for (int k = 0; k < 32; k++) {
            float4 b0 = *(float4*)&Bs[k][tx*4];
            float4 b1 = *(float4*)&Bs[k][128 + tx*4];
            ull bp0 = pack2(b0.x,b0.y), bp1 = pack2(b0.z,b0.w);
            ull bp2 = pack2(b1.x,b1.y), bp3 = pack2(b1.z,b1.w);
            #pragma unroll
            for (int q = 0; q < 8; q++) {
                float a = As[k][ty*8 + q];       // warp-broadcast LDS
                ull aa = pack2(a, a);
                fma2(acc[q][0], aa, bp0); fma2(acc[q][1], aa, bp1);
                fma2(acc[q][2], aa, bp2); fma2(acc[q][3], aa, bp3);
            }
        }
        __syncthreads();
    }

    // A tile dead: alias its smem as w2s (256*9 floats = 9216 B = sizeof(As)).
    float* w2s = &As[0][0];
    for (int idx = tid; idx < 2048; idx += 256) {
        int h = idx >> 3, e = idx & 7;
        w2s[h*9 + e] = __ldg(&w2[idx]);
    }
    // (visibility of w2s ensured by the __syncthreads() inside the half loop)

    // Epilogue in two 32-row halves; hidden lives in Bs (reused as Hs).
    float (*Hs)[264] = (float(*)[264])Bs;
    #pragma unroll
    for (int half = 0; half < 2; half++) {
        if ((ty >> 2) == half) {
            int tyl = ty & 3;
            #pragma unroll
            for (int q = 0; q < 8; q++) {
                int rl = tyl*8 + q;                    // local row 0..31
                const float* bb = g_biasb + sB[half*32 + rl]*256;
                float h[8];
                unpack2(acc[q][0], h[0], h[1]);
                unpack2(acc[q][1], h[2], h[3]);
                unpack2(acc[q][2], h[4], h[5]);
                unpack2(acc[q][3], h[6], h[7]);
                #pragma unroll
                for (int c = 0; c < 4; c++) {
                    int col = tx*4 + c;
                    Hs[rl][col] = fmaxf(h[c] + __ldg(&bb[col]), 0.f);
                }
                #pragma unroll
                for (int c = 0; c < 4; c++) {
                    int col = 128 + tx*4 + c;
                    Hs[rl][col] = fmaxf(h[c+4] + __ldg(&bb[col]), 0.f);
                }
            }
        }
        __syncthreads();
        int rl = tid >> 3, e = tid & 7;
        int gidx = m0 + half*32 + rl;
        if (gidx < cnt) {
            float s = 0.f;
            const float* hrow = Hs[rl];
            #pragma unroll 8
            for (int h = 0; h < 256; h++) s += hrow[h] * w2s[h*9 + e];
            out[(size_t)sRow[half*32 + rl]*8 + e] = s + __ldg(&b2[e]);
        }
        __syncthreads();
    }
}

// ============================================================
extern "C" void kernel_launch(void* const* d_in, const int* in_sizes, int n_in,
                              void* d_out, int out_size)
{
    const float* feat_body    = (const float*)d_in[0];
    const float* feat_img_1   = (const float*)d_in[1];
    const float* feat_img_2   = (const float*)d_in[2];
    const float* feat_img_ssl = (const float*)d_in[3];
    const int*   full_mask    = (const int*)  d_in[4];
    const float* img_fc_w     = (const float*)d_in[5];
    const float* img_fc_b     = (const float*)d_in[6];
    const float* node_fc_w    = (const float*)d_in[7];
    const float* node_fc_b    = (const float*)d_in[8];
    const float* edge_fc_w1   = (const float*)d_in[9];
    const float* edge_fc_b1   = (const float*)d_in[10];
    const float* edge_fc_w2   = (const float*)d_in[11];
    const float* edge_fc_b2   = (const float*)d_in[12];
    float* out = (float*)d_out;

    void *pv;
    float *p_prop, *p_msg, *p_Wc, *p_fi2v, *p_fsslv;
    cudaGetSymbolAddress(&pv, g_prop);  p_prop  = (float*)pv;
    cudaGetSymbolAddress(&pv, g_msg);   p_msg   = (float*)pv;
    cudaGetSymbolAddress(&pv, g_Wc);    p_Wc    = (float*)pv;
    cudaGetSymbolAddress(&pv, g_fi2v);  p_fi2v  = (float*)pv;
    cudaGetSymbolAddress(&pv, g_fsslv); p_fsslv = (float*)pv;

    reset_kernel<<<1, 1>>>();
    compact_kernel<<<ROWS/256, 256>>>(full_mask, out);

    // prop0 = feat_body @ img_fc_w + img_fc_b
    gemm_kernel<<<dim3(32, 4), 256>>>(feat_body, img_fc_w, img_fc_b, p_prop,
                                      Bb*Nn, Hh);
    // scan
    for (int t = 0; t < Tt; t++) {
        gemm_kernel<<<dim3(32, 4), 256>>>(p_prop, node_fc_w + (size_t)t*Hh*Hh,
                                          node_fc_b + t*Hh,
                                          p_msg + (size_t)t*BNH, Bb*Nn, Hh);
        if (t < Tt - 1) agg_kernel<<<Bb*Nn, 256>>>(t, full_mask);
    }

    // folded weights / per-batch bias
    gemm_kernel<<<dim3(8, 4), 256>>>(img_fc_w, edge_fc_w1 + (size_t)Hh*Hh,
                                     nullptr, p_Wc, Hh, Hh);
    gemm_kernel<<<dim3(1, 4), 256>>>(feat_img_2, img_fc_w, img_fc_b, p_fi2v,
                                     Bb, Hh);
    gemm_kernel<<<dim3(1, 4), 256>>>(feat_img_ssl, img_fc_w, img_fc_b, p_fsslv,
                                     Bb, Hh);
    biask_kernel<<<dim3(Bb, 4), 256>>>(edge_fc_b1, img_fc_b, edge_fc_w1);

    // gather A rows, then fuse_v3b
    gather_kernel<<<ROWS, 256>>>(feat_img_1);
    fuse_kernel<<<ROWS/64, 256>>>(edge_fc_w1, edge_fc_w2, edge_fc_b2, out);
}

// round 11
// speedup vs baseline: 1.4167x; 1.1705x over previous
#include <cuda_runtime.h>
#include <cstdint>

#define Bb 16
#define Nn 64
#define Hh 256
#define Tt 5
#define ROWS (Bb*Nn*Nn)      // 65536 (b,i,j) rows   [NB: 16*64*64]
#define BNH  (Bb*Nn*Hh)      // 262144

typedef unsigned long long ull;

// ---- device scratch ----
__device__ float g_prop [BNH];
__device__ float g_msg  [Tt*BNH];
__device__ float g_Wc   [Hh*Hh];
__device__ float g_fi2v [Bb*Hh];
__device__ float g_fsslv[Bb*Hh];
__device__ float g_biasb[Bb*Hh];
__device__ int   g_rows [ROWS];
__device__ unsigned g_maskb[ROWS/32];   // 2048 words
__device__ int   g_count;

// ---- packed f32x2 helpers ----
__device__ __forceinline__ ull pack2(float lo, float hi) {
    ull r; asm("mov.b64 %0, {%1,%2};" : "=l"(r) : "f"(lo), "f"(hi)); return r;
}
__device__ __forceinline__ void fma2(ull& d, ull a, ull b) {
    asm("fma.rn.f32x2 %0, %1, %2, %0;" : "+l"(d) : "l"(a), "l"(b));
}
__device__ __forceinline__ void unpack2(ull v, float& lo, float& hi) {
    asm("mov.b64 {%0,%1}, %2;" : "=f"(lo), "=f"(hi) : "l"(v));
}

// ---- cp.async helpers ----
__device__ __forceinline__ uint32_t sptr(const void* p) {
    return (uint32_t)__cvta_generic_to_shared(p);
}
__device__ __forceinline__ void cpa16(uint32_t dst, const void* src, int szbytes) {
    asm volatile("cp.async.ca.shared.global [%0], [%1], 16, %2;"
                 :: "r"(dst), "l"(src), "r"(szbytes));
}
#define CP_COMMIT() asm volatile("cp.async.commit_group;")
template<int N> __device__ __forceinline__ void cp_wait() {
    asm volatile("cp.async.wait_group %0;" :: "n"(N));
}

// ============================================================
// Device GEMM body [R2-validated gemm_kernel with m0/n0 as params]
// C[m0:m0+32, n0:n0+64] = A[M,K] @ W[K,256] (+bias)
// ============================================================
__device__ void dev_gemm(
    const float* __restrict__ A, const float* __restrict__ W,
    const float* __restrict__ bias, float* __restrict__ C,
    int M, int K, int m0, int n0)
{
    __shared__ __align__(16) float AS[2][32][36];
    __shared__ __align__(16) float BS[2][32][64];
    int tid = threadIdx.x;

    int ar = tid >> 3, ac = tid & 7;
    int bk0 = tid >> 4, bc0 = tid & 15;

    auto issue = [&](int s, int k0) {
        bool aok = (m0 + ar) < M;
        const float* asrc = A + (size_t)(aok ? (m0 + ar) : 0) * K + k0 + ac*4;
        cpa16(sptr(&AS[s][ar][ac*4]), asrc, aok ? 16 : 0);
        #pragma unroll
        for (int q = 0; q < 2; q++) {
            int kk = bk0 + q*16;
            cpa16(sptr(&BS[s][kk][bc0*4]), W + (size_t)(k0+kk)*256 + n0 + bc0*4, 16);
        }
        CP_COMMIT();
    };

    int tx = tid & 15, ty = tid >> 4;
    ull acc[2][2] = {};

    issue(0, 0);
    int nt = K >> 5;
    for (int t = 0; t < nt; t++) {
        if (t + 1 < nt) { issue((t+1)&1, (t+1)*32); cp_wait<1>(); }
        else            { cp_wait<0>(); }
        __syncthreads();
        int s = t & 1;
        #pragma unroll
        for (int k = 0; k < 32; k++) {
            float a0 = AS[s][ty*2+0][k];
            float a1 = AS[s][ty*2+1][k];
            float4 b = *(float4*)&BS[s][k][tx*4];
            ull bp0 = pack2(b.x, b.y), bp1 = pack2(b.z, b.w);
            ull aa0 = pack2(a0, a0),   aa1 = pack2(a1, a1);
            fma2(acc[0][0], aa0, bp0); fma2(acc[0][1], aa0, bp1);
            fma2(acc[1][0], aa1, bp0); fma2(acc[1][1], aa1, bp1);
        }
        __syncthreads();
    }

    #pragma unroll
    for (int q = 0; q < 2; q++) {
        int gr = m0 + ty*2 + q;
        if (gr < M) {
            float v[4];
            unpack2(acc[q][0], v[0], v[1]);
            unpack2(acc[q][1], v[2], v[3]);
            #pragma unroll
            for (int c = 0; c < 4; c++) {
                int gc = n0 + tx*4 + c;
                float o = v[c];
                if (bias) o += bias[gc];
                C[(size_t)gr*256 + gc] = o;
            }
        }
    }
}

// ============================================================
// L1: mega0 — prop0 || Wc || fi2v || fsslv || zero g_count  (169 blocks)
// ============================================================
__global__ __launch_bounds__(256) void mega0_kernel(
    const float* __restrict__ feat_body,
    const float* __restrict__ img_fc_w, const float* __restrict__ img_fc_b,
    const float* __restrict__ feat_img_2, const float* __restrict__ feat_img_ssl,
    const float* __restrict__ edge_fc_w1)
{
    int blk = blockIdx.x;
    if (blk == 168) { if (threadIdx.x == 0) g_count = 0; return; }

    const float *A, *W, *bias; float* C; int M, m0, n0;
    if (blk < 128) {            // prop0: [1024,256] = feat_body @ img_fc_w + b
        A = feat_body; W = img_fc_w; bias = img_fc_b; C = g_prop;
        M = Bb*Nn; m0 = (blk >> 2) * 32; n0 = (blk & 3) * 64;
    } else if (blk < 160) {     // Wc: [256,256] = img_fc_w @ w1[256:512]
        int b2 = blk - 128;
        A = img_fc_w; W = edge_fc_w1 + 256*256; bias = nullptr; C = g_Wc;
        M = 256; m0 = (b2 >> 2) * 32; n0 = (b2 & 3) * 64;
    } else if (blk < 164) {     // fi2v: [16,256]
        A = feat_img_2; W = img_fc_w; bias = img_fc_b; C = g_fi2v;
        M = Bb; m0 = 0; n0 = (blk - 160) * 64;
    } else {                    // fsslv: [16,256]
        A = feat_img_ssl; W = img_fc_w; bias = img_fc_b; C = g_fsslv;
        M = Bb; m0 = 0; n0 = (blk - 164) * 64;
    }
    dev_gemm(A, W, bias, C, M, 256, m0, n0);
}

// ============================================================
// L2: mega1 — compact (256 blocks: FULL 65536 rows) || biask (64 blocks)
// grid 320: blk<256 compact, else biask.
// ============================================================
__global__ __launch_bounds__(256) void mega1_kernel(
    const int* __restrict__ mask, float* __restrict__ out,
    const float* __restrict__ b1, const float* __restrict__ bimg,
    const float* __restrict__ w1)
{
    int blk = blockIdx.x;
    if (blk < 256) {
        int r = blk * 256 + threadIdx.x;          // 0..65535  (FIXED)
        float4 z = make_float4(0.f, 0.f, 0.f, 0.f);
        float4* o = (float4*)(out + (size_t)r * 8);
        o[0] = z; o[1] = z;
        bool act = (mask[r] != 0);
        unsigned bal = __ballot_sync(0xffffffffu, act);
        if ((threadIdx.x & 31) == 0) g_maskb[r >> 5] = bal;
        if (act) {
            int p = atomicAdd(&g_count, 1);
            g_rows[p] = r;
        }
    } else {
        int b  = (blk - 256) >> 2;
        int ny = (blk - 256) & 3;
        int n = ny*64 + (threadIdx.x & 63);
        int part = threadIdx.x >> 6;
        __shared__ float red[4][64];
        const float* f2 = g_fi2v  + b*256;
        const float* f3 = g_fsslv + b*256;
        float s = 0.f;
        for (int h = part; h < 256; h += 4) {
            s += bimg[h] * __ldg(&w1[(256+h)*256 + n]);
            s += f2[h]   * __ldg(&w1[(512+h)*256 + n]);
            s += f3[h]   * __ldg(&w1[(768+h)*256 + n]);
        }
        red[part][threadIdx.x & 63] = s;
        __syncthreads();
        if (part == 0) {
            int l = threadIdx.x & 63;
            g_biasb[b*256 + n] = b1[n] + red[0][l] + red[1][l] + red[2][l] + red[3][l];
        }
    }
}

// ============================================================
// L3-L7: fused scan step [R3-validated]
// grid (16, 8), 256 threads.
// ============================================================
__global__ __launch_bounds__(256) void scan_kernel(
    const float* __restrict__ W, const float* __restrict__ bias,
    int t, int do_agg)
{
    __shared__ __align__(16) float AS[2][64][36];
    __shared__ __align__(16) float BS[2][32][36];
    __shared__ float msgT[32][65];     // [local col][row j]
    __shared__ unsigned smask[128];

    int b  = blockIdx.x;
    int n0 = blockIdx.y * 32;
    int tid = threadIdx.x;
    const float* Ab = g_prop + (size_t)b * 64 * 256;

    if (do_agg && tid < 128) smask[tid] = g_maskb[b*128 + tid];

    auto issue = [&](int s, int k0) {
        #pragma unroll
        for (int p = 0; p < 2; p++) {
            int cid = p*256 + tid; int rr = cid >> 3, cc = cid & 7;
            cpa16(sptr(&AS[s][rr][cc*4]), Ab + (size_t)rr*256 + k0 + cc*4, 16);
        }
        int rr = tid >> 3, cc = tid & 7;
        cpa16(sptr(&BS[s][rr][cc*4]), W + (size_t)(k0 + rr)*256 + n0 + cc*4, 16);
        CP_COMMIT();
    };

    int tx = tid & 15, ty = tid >> 4;   // 2 cols, 4 rows per thread
    ull acc[4] = {};

    issue(0, 0);
    for (int kt = 0; kt < 8; kt++) {
        if (kt + 1 < 8) { issue((kt+1)&1, (kt+1)*32); cp_wait<1>(); }
        else            { cp_wait<0>(); }
        __syncthreads();
        int s = kt & 1;
        #pragma unroll
        for (int k = 0; k < 32; k++) {
            float2 bv = *(float2*)&BS[s][k][tx*2];
            ull bp = pack2(bv.x, bv.y);
            #pragma unroll
            for (int q = 0; q < 4; q++) {
                float a = AS[s][ty*4+q][k];
                fma2(acc[q], pack2(a, a), bp);
            }
        }
        __syncthreads();
    }

    float b0 = bias[n0 + tx*2], b1 = bias[n0 + tx*2 + 1];
    float* msgg = g_msg + ((size_t)t*Bb + b) * 64 * 256;
    #pragma unroll
    for (int q = 0; q < 4; q++) {
        int row = ty*4 + q;
        float v0, v1;
        unpack2(acc[q], v0, v1);
        v0 += b0; v1 += b1;
        msgT[tx*2    ][row] = v0;
        msgT[tx*2 + 1][row] = v1;
        *(float2*)&msgg[(size_t)row*256 + n0 + tx*2] = make_float2(v0, v1);
    }
    __syncthreads();

    if (do_agg) {
        int i = tid >> 2, hg = tid & 3;     // i: row, hg: 8-col group
        float mi[8], av[8];
        #pragma unroll
        for (int hh = 0; hh < 8; hh++) { mi[hh] = msgT[hg*8+hh][i]; av[hh] = 0.f; }
        unsigned w0 = smask[i*2], w1m = smask[i*2 + 1];
        #pragma unroll 4
        for (int j = 0; j < 32; j++) {
            if ((w0 >> j) & 1) {
                #pragma unroll
                for (int hh = 0; hh < 8; hh++) {
                    float mj = msgT[hg*8+hh][j];
                    av[hh] += fmaxf(mi[hh] + mj, 0.f) * mj;
                }
            }
        }
        #pragma unroll 4
        for (int j = 0; j < 32; j++) {
            if ((w1m >> j) & 1) {
                #pragma unroll
                for (int hh = 0; hh < 8; hh++) {
                    float mj = msgT[hg*8+hh][j + 32];
                    av[hh] += fmaxf(mi[hh] + mj, 0.f) * mj;
                }
            }
        }
        float* pr = g_prop + ((size_t)b*64 + i)*256 + n0 + hg*8;
        #pragma unroll
        for (int hh = 0; hh < 8; hh++)
            pr[hh] += fmaxf(mi[hh] + av[hh], 0.f);
    }
}

// ============================================================
// L8: fuse_v4 — R9-validated BM64/BK32 mainloop + smem epilogue,
// R2-validated in-loop A-gen (maxpool | fimg1).
// ============================================================
__global__ __launch_bounds__(256) void fuse_kernel(
    const float* __restrict__ fimg1, const float* __restrict__ w1,
    const float* __restrict__ w2,    const float* __restrict__ b2,
    float* __restrict__ out)
{
    __shared__ __align__(16) float Bs[32][264];  // [k][n]; reused as Hs
    __shared__ __align__(16) float As[32][72];   // [k][row]; reused as w2s
    __shared__ int sRow[64], sB[64], sBI[64], sBJ[64];

    int cnt = g_count;
    int m0  = blockIdx.x * 64;
    if (m0 >= cnt) return;
    int tid = threadIdx.x;

    if (tid < 64) {
        int cl  = min(m0 + tid, cnt - 1);
        int row = g_rows[cl];
        int b = row >> 12, i = (row >> 6) & 63, j = row & 63;
        sRow[tid] = row;
        sB[tid]   = b;
        sBI[tid]  = (b*64 + i) * 256;
        sBJ[tid]  = (b*64 + j) * 256;
    }
    __syncthreads();

    int tx = tid & 31, ty = tid >> 5;
    ull acc[8][4];
    #pragma unroll
    for (int q = 0; q < 8; q++)
        #pragma unroll
        for (int c = 0; c < 4; c++) acc[q][c] = 0ULL;

    for (int k0 = 0; k0 < 512; k0 += 32) {
        const float* Bsrc = (k0 < 256) ? (w1 + (size_t)k0*256)
                                       : (g_Wc + (size_t)(k0-256)*256);
        #pragma unroll
        for (int p = 0; p < 8; p++) {
            int c = p*256 + tid; int kk = c >> 6, c4 = c & 63;
            *(float4*)&Bs[kk][c4*4] = *(const float4*)&Bsrc[(size_t)kk*256 + c4*4];
        }
        if (k0 < 256) {
            #pragma unroll
            for (int p = 0; p < 8; p++) {
                int lin = p*256 + tid; int r = lin >> 5, kk = lin & 31;
                int k = k0 + kk;
                const float* mi = g_msg + sBI[r] + k;
                const float* mj = g_msg + sBJ[r] + k;
                float m = mi[0] + mj[0];
                #pragma unroll
                for (int t = 1; t < Tt; t++)
                    m = fmaxf(m, mi[(size_t)t*BNH] + mj[(size_t)t*BNH]);
                As[kk][r] = fmaxf(m, 0.f);
            }
        } else {
            #pragma unroll
            for (int p = 0; p < 8; p++) {
                int lin = p*256 + tid; int r = lin >> 5, kk = lin & 31;
                As[kk][r] = __ldg(&fimg1[(size_t)sRow[r]*256 + (k0-256) + kk]);
            }
        }
        __syncthreads();
        #pragma unroll
        for (int k = 0; k < 32; k++) {
            float4 b0 = *(float4*)&Bs[k][tx*4];
            float4 b1 = *(float4*)&Bs[k][128 + tx*4];
            ull bp0 = pack2(b0.x,b0.y), bp1 = pack2(b0.z,b0.w);
            ull bp2 = pack2(b1.x,b1.y), bp3 = pack2(b1.z,b1.w);
            #pragma unroll
            for (int q = 0; q < 8; q++) {
                float a = As[k][ty*8 + q];       // warp-broadcast LDS
                ull aa = pack2(a, a);
                fma2(acc[q][0], aa, bp0); fma2(acc[q][1], aa, bp1);
                fma2(acc[q][2], aa, bp2); fma2(acc[q][3], aa, bp3);
            }
        }
        __syncthreads();
    }

    // A tile dead: alias its smem as w2s (256*9 floats = 9216 B).
    float* w2s = &As[0][0];
    for (int idx = tid; idx < 2048; idx += 256) {
        int h = idx >> 3, e = idx & 7;
        w2s[h*9 + e] = __ldg(&w2[idx]);
    }

    float (*Hs)[264] = (float(*)[264])Bs;
    #pragma unroll
    for (int half = 0; half < 2; half++) {
        if ((ty >> 2) == half) {
            int tyl = ty & 3;
            #pragma unroll
            for (int q = 0; q < 8; q++) {
                int rl = tyl*8 + q;
                const float* bb = g_biasb + sB[half*32 + rl]*256;
                float h[8];
                unpack2(acc[q][0], h[0], h[1]);
                unpack2(acc[q][1], h[2], h[3]);
                unpack2(acc[q][2], h[4], h[5]);
                unpack2(acc[q][3], h[6], h[7]);
                #pragma unroll
                for (int c = 0; c < 4; c++) {
                    int col = tx*4 + c;
                    Hs[rl][col] = fmaxf(h[c] + __ldg(&bb[col]), 0.f);
                }
                #pragma unroll
                for (int c = 0; c < 4; c++) {
                    int col = 128 + tx*4 + c;
                    Hs[rl][col] = fmaxf(h[c+4] + __ldg(&bb[col]), 0.f);
                }
            }
        }
        __syncthreads();
        int rl = tid >> 3, e = tid & 7;
        int gidx = m0 + half*32 + rl;
        if (gidx < cnt) {
            float s = 0.f;
            const float* hrow = Hs[rl];
            #pragma unroll 8
            for (int h = 0; h < 256; h++) s += hrow[h] * w2s[h*9 + e];
            out[(size_t)sRow[half*32 + rl]*8 + e] = s + __ldg(&b2[e]);
        }
        __syncthreads();
    }
}

// ============================================================
extern "C" void kernel_launch(void* const* d_in, const int* in_sizes, int n_in,
                              void* d_out, int out_size)
{
    const float* feat_body    = (const float*)d_in[0];
    const float* feat_img_1   = (const float*)d_in[1];
    const float* feat_img_2   = (const float*)d_in[2];
    const float* feat_img_ssl = (const float*)d_in[3];
    const int*   full_mask    = (const int*)  d_in[4];
    const float* img_fc_w     = (const float*)d_in[5];
    const float* img_fc_b     = (const float*)d_in[6];
    const float* node_fc_w    = (const float*)d_in[7];
    const float* node_fc_b    = (const float*)d_in[8];
    const float* edge_fc_w1   = (const float*)d_in[9];
    const float* edge_fc_b1   = (const float*)d_in[10];
    const float* edge_fc_w2   = (const float*)d_in[11];
    const float* edge_fc_b2   = (const float*)d_in[12];
    float* out = (float*)d_out;

    // L1: prop0 || Wc || fi2v || fsslv || zero-count
    mega0_kernel<<<169, 256>>>(feat_body, img_fc_w, img_fc_b,
                               feat_img_2, feat_img_ssl, edge_fc_w1);
    // L2: compact (FULL 65536 rows) || biask
    mega1_kernel<<<320, 256>>>(full_mask, out, edge_fc_b1, img_fc_b, edge_fc_w1);
    // L3-L7: fused scan steps
    for (int t = 0; t < Tt; t++)
        scan_kernel<<<dim3(Bb, 8), 256>>>(node_fc_w + (size_t)t*Hh*Hh,
                                          node_fc_b + t*Hh, t, t < Tt-1);
    // L8: fused final GEMM + epilogue
    fuse_kernel<<<ROWS/64, 256>>>(feat_img_1, edge_fc_w1, edge_fc_w2,
                                  edge_fc_b2, out);
}